// round 1
// baseline (speedup 1.0000x reference)
#include <cuda_runtime.h>
#include <cstdint>

// Problem dims (fixed by dataset)
#define NQ1   10001     // q vocab  (0..10000)
#define NQA1  20001     // qa vocab (0..20000)
#define MSZ   64        // memory slots
#define KD    128       // key dim
#define VD    256       // value emb dim
#define VM    256       // memory value dim
#define FD    128       // feature dim
#define BB    512       // batch
#define SS    512       // seq len

// ---------------------------------------------------------------------------
// Scratch tables (static __device__: allocation rules forbid cudaMalloc)
// ---------------------------------------------------------------------------
__device__ float g_wtab [NQ1  * MSZ];   //  2.56 MB : softmax(k . Mk^T)
__device__ float g_fktab[NQ1  * FD ];   //  5.12 MB : bf + Wf_k . k
__device__ float g_etab [NQA1 * VM ];   // 20.5  MB : sigmoid(We . v + be)
__device__ float g_atab [NQA1 * VM ];   // 20.5  MB : tanh(Wa . v + ba)

// ---------------------------------------------------------------------------
// Kernel A: per-q-index tables  w_table, fk_table.   grid = NQ1, block = 128
// ---------------------------------------------------------------------------
__global__ void __launch_bounds__(128)
build_wfk_kernel(const float* __restrict__ k_emb, const float* __restrict__ Mk,
                 const float* __restrict__ Wf,    const float* __restrict__ bf)
{
    __shared__ float k_s[KD];
    __shared__ float sc [MSZ];
    const int i   = blockIdx.x;
    const int tid = threadIdx.x;

    if (tid < KD) k_s[tid] = k_emb[i * KD + tid];
    __syncthreads();

    if (tid < MSZ) {
        const float* mk = Mk + tid * KD;
        float s = 0.f;
        #pragma unroll 8
        for (int j = 0; j < KD; j++) s = fmaf(mk[j], k_s[j], s);
        sc[tid] = s;
    }
    __syncthreads();

    if (tid < MSZ) {
        float mx = -1e30f;
        for (int m = 0; m < MSZ; m++) mx = fmaxf(mx, sc[m]);
        float sum = 0.f;
        for (int m = 0; m < MSZ; m++) sum += expf(sc[m] - mx);
        g_wtab[i * MSZ + tid] = expf(sc[tid] - mx) / sum;
    }

    // fk[f] = bf[f] + Wf[f, 256:384] . k     (concat order is [r(256), k(128)])
    {
        const float* wfk = Wf + tid * (KD + VM) + VM;
        float s = bf[tid];
        #pragma unroll 8
        for (int j = 0; j < KD; j++) s = fmaf(wfk[j], k_s[j], s);
        g_fktab[i * FD + tid] = s;
    }
}

// ---------------------------------------------------------------------------
// Kernel B: per-qa-index tables e_table, a_table (fused GEMM).
// grid = ceil(NQA1/32), block = 256. Thread u computes outputs for 32 indices.
// ---------------------------------------------------------------------------
#define TI 32
__global__ void __launch_bounds__(256)
build_ea_kernel(const float* __restrict__ v_emb,
                const float* __restrict__ We, const float* __restrict__ be,
                const float* __restrict__ Wa, const float* __restrict__ ba)
{
    __shared__ float4 v_s[TI * (VD / 4)];   // 32 KB
    const int tid  = threadIdx.x;
    const int base = blockIdx.x * TI;

    for (int idx = tid; idx < TI * (VD / 4); idx += 256) {
        const int i  = idx / (VD / 4);
        const int j4 = idx % (VD / 4);
        const int gi = base + i;
        float4 v = make_float4(0.f, 0.f, 0.f, 0.f);
        if (gi < NQA1)
            v = reinterpret_cast<const float4*>(v_emb)[gi * (VD / 4) + j4];
        v_s[i * (VD / 4) + j4] = v;
    }
    __syncthreads();

    const int u = tid;   // output row 0..255
    float acce[TI], acca[TI];
    #pragma unroll
    for (int i = 0; i < TI; i++) { acce[i] = 0.f; acca[i] = 0.f; }

    const float4* we4 = reinterpret_cast<const float4*>(We + u * VD);
    const float4* wa4 = reinterpret_cast<const float4*>(Wa + u * VD);

    for (int j4 = 0; j4 < VD / 4; j4++) {
        const float4 we = we4[j4];
        const float4 wa = wa4[j4];
        #pragma unroll
        for (int i = 0; i < TI; i++) {
            const float4 v = v_s[i * (VD / 4) + j4];   // warp-broadcast LDS.128
            acce[i] = fmaf(we.x, v.x, fmaf(we.y, v.y, fmaf(we.z, v.z, fmaf(we.w, v.w, acce[i]))));
            acca[i] = fmaf(wa.x, v.x, fmaf(wa.y, v.y, fmaf(wa.z, v.z, fmaf(wa.w, v.w, acca[i]))));
        }
    }

    const float bei = be[u], bai = ba[u];
    for (int i = 0; i < TI; i++) {
        const int gi = base + i;
        if (gi < NQA1) {
            g_etab[gi * VM + u] = 1.f / (1.f + expf(-(acce[i] + bei)));
            g_atab[gi * VM + u] = tanhf(acca[i] + bai);
        }
    }
}

// ---------------------------------------------------------------------------
// Main sequential kernel: one CTA per batch. Thread u owns Mv[:,u] in regs.
// smem: Wf_r^T in float4 block layout (128 KB) + r/w/partials/q/qa (9.4 KB)
// ---------------------------------------------------------------------------
#define SM_WF      0                    // 8192 float4 = 131072 B
#define SM_R       131072               // 256 floats  (16B aligned)
#define SM_W       (131072 + 1024)      // 64 floats
#define SM_FP      (131072 + 1024 + 256)// 256 floats
#define SM_Q       (131072 + 2304)      // 512 ints
#define SM_QA      (131072 + 2304 + 2048)
#define SMEM_BYTES (131072 + 2304 + 4096)

__global__ void __launch_bounds__(256, 1)
dkvmn_main_kernel(const int* __restrict__ q,  const int* __restrict__ qa,
                  const float* __restrict__ Wf, const float* __restrict__ Wp,
                  const float* __restrict__ bp, const float* __restrict__ Mv0,
                  float* __restrict__ out)
{
    extern __shared__ char smem[];
    float4* s_Wf4 = reinterpret_cast<float4*>(smem + SM_WF);
    float*  s_r   = reinterpret_cast<float*>(smem + SM_R);
    float*  s_w   = reinterpret_cast<float*>(smem + SM_W);
    float*  s_fp  = reinterpret_cast<float*>(smem + SM_FP);
    int*    s_q   = reinterpret_cast<int*>(smem + SM_Q);
    int*    s_qa  = reinterpret_cast<int*>(smem + SM_QA);

    const int b   = blockIdx.x;
    const int tid = threadIdx.x;
    const int f   = tid & 127;   // phase-B output index
    const int h   = tid >> 7;    // phase-B u-half

    // Stage q/qa for this batch
    for (int idx = tid; idx < SS; idx += 256) {
        s_q [idx] = q [b * SS + idx];
        s_qa[idx] = qa[b * SS + idx];
    }

    // Stage Wf_r^T in a float4-block layout:
    //   element (f,u) -> ((u/4)*FD + f) float4, lane u%4.
    // Phase-B read: thread f reads s_Wf4[ub*FD + f] -> consecutive threads,
    // consecutive float4s -> conflict-free LDS.128.
    for (int idx = tid; idx < FD * VM; idx += 256) {
        const int ff = idx >> 8;        // f  = idx / 256
        const int u  = idx & 255;       // u  = idx % 256
        reinterpret_cast<float*>(s_Wf4)[((u >> 2) * FD + ff) * 4 + (u & 3)]
            = Wf[ff * (KD + VM) + u];
    }

    // Register-resident state: Mv[m][tid], m = 0..63
    float Mv[MSZ];
    #pragma unroll
    for (int m = 0; m < MSZ; m++) Mv[m] = Mv0[m * VM + tid];

    const float wp_f = Wp[f];
    const float bp0  = bp[0];

    __syncthreads();

    // Software-prefetch t = 0 gathers
    int qt = s_q[0], qat = s_qa[0];
    float e_n  = g_etab [qat * VM + tid];
    float a_n  = g_atab [qat * VM + tid];
    float fk_n = g_fktab[qt * FD + f];
    float w_n  = (tid < MSZ) ? g_wtab[qt * MSZ + tid] : 0.f;

    for (int t = 0; t < SS; t++) {
        const float e_u = e_n, a_u = a_n, fk_u = fk_n;
        if (tid < MSZ) s_w[tid] = w_n;
        __syncthreads();                      // (a) s_w ready

        // Prefetch next step's gathers (L2 hit, hidden behind phase A/B)
        if (t + 1 < SS) {
            const int qn = s_q[t + 1], qan = s_qa[t + 1];
            e_n  = g_etab [qan * VM + tid];
            a_n  = g_atab [qan * VM + tid];
            fk_n = g_fktab[qn * FD + f];
            if (tid < MSZ) w_n = g_wtab[qn * MSZ + tid];
        }

        // ---- Phase A: r = w.Mv (old state), Mv += w*(a - e*Mv) -------------
        float r_u = 0.f;
        #pragma unroll
        for (int m = 0; m < MSZ; m++) {
            const float wm = s_w[m];          // warp-broadcast LDS
            const float mv = Mv[m];
            r_u   = fmaf(wm, mv, r_u);
            Mv[m] = fmaf(wm, fmaf(-e_u, mv, a_u), mv);
        }
        s_r[tid] = r_u;
        __syncthreads();                      // (b) s_r ready

        // ---- Phase B: partial f = Wf_r . r  (split u-range across 2 halves)
        float acc = (h == 0) ? fk_u : 0.f;
        const float4* s_r4 = reinterpret_cast<const float4*>(s_r);
        #pragma unroll
        for (int u4 = 0; u4 < 32; u4++) {
            const int ub = h * 32 + u4;
            const float4 wv = s_Wf4[ub * FD + f];   // conflict-free
            const float4 rv = s_r4[ub];             // broadcast
            acc = fmaf(wv.x, rv.x, fmaf(wv.y, rv.y, fmaf(wv.z, rv.z, fmaf(wv.w, rv.w, acc))));
        }
        s_fp[tid] = acc;
        __syncthreads();                      // (c) partials ready

        // ---- tanh + Wp projection ------------------------------------------
        if (tid < FD) {
            const float fv = tanhf(s_fp[tid] + s_fp[tid + 128]);
            s_fp[tid] = wp_f * fv;
        }
        __syncthreads();                      // (d) terms ready

        if (tid < 32) {
            float v = s_fp[tid] + s_fp[tid + 32] + s_fp[tid + 64] + s_fp[tid + 96];
            #pragma unroll
            for (int o = 16; o > 0; o >>= 1) v += __shfl_xor_sync(0xffffffffu, v, o);
            if (tid == 0) out[b * SS + t] = v + bp0;
        }
    }
}

// ---------------------------------------------------------------------------
// Launch. Inputs (metadata order): q, qa, k_emb, v_emb, Wf, bf, Wp, bp,
//                                  We, be, Wa, ba, Mk, Mv0
// ---------------------------------------------------------------------------
extern "C" void kernel_launch(void* const* d_in, const int* in_sizes, int n_in,
                              void* d_out, int out_size)
{
    const int*   q     = (const int*)  d_in[0];
    const int*   qa    = (const int*)  d_in[1];
    const float* k_emb = (const float*)d_in[2];
    const float* v_emb = (const float*)d_in[3];
    const float* Wf    = (const float*)d_in[4];
    const float* bf    = (const float*)d_in[5];
    const float* Wp    = (const float*)d_in[6];
    const float* bp    = (const float*)d_in[7];
    const float* We    = (const float*)d_in[8];
    const float* be    = (const float*)d_in[9];
    const float* Wa    = (const float*)d_in[10];
    const float* ba    = (const float*)d_in[11];
    const float* Mk    = (const float*)d_in[12];
    const float* Mv0   = (const float*)d_in[13];
    float* out = (float*)d_out;

    static bool attr_done = false;
    if (!attr_done) {
        cudaFuncSetAttribute(dkvmn_main_kernel,
                             cudaFuncAttributeMaxDynamicSharedMemorySize, SMEM_BYTES);
        attr_done = true;
    }

    build_wfk_kernel<<<NQ1, 128>>>(k_emb, Mk, Wf, bf);
    build_ea_kernel<<<(NQA1 + TI - 1) / TI, 256>>>(v_emb, We, be, Wa, ba);
    dkvmn_main_kernel<<<BB, 256, SMEM_BYTES>>>(q, qa, Wf, Wp, bp, Mv0, out);
}

// round 2
// speedup vs baseline: 1.6181x; 1.6181x over previous
#include <cuda_runtime.h>
#include <cstdint>

// Problem dims (fixed by dataset)
#define NQ1   10001
#define NQA1  20001
#define MSZ   64
#define KD    128
#define VD    256
#define VM    256
#define FD    128
#define BB    512
#define SS    512

typedef unsigned long long ull;

// ---------------------------------------------------------------------------
// f32x2 packed-math helpers (sm_100a)
// ---------------------------------------------------------------------------
__device__ __forceinline__ ull pk2(float a, float b) {
    ull r; asm("mov.b64 %0, {%1, %2};" : "=l"(r) : "f"(a), "f"(b)); return r;
}
__device__ __forceinline__ void upk2(ull p, float& a, float& b) {
    asm("mov.b64 {%0, %1}, %2;" : "=f"(a), "=f"(b) : "l"(p));
}
__device__ __forceinline__ ull fma2(ull a, ull b, ull c) {
    ull d; asm("fma.rn.f32x2 %0, %1, %2, %3;" : "=l"(d) : "l"(a), "l"(b), "l"(c)); return d;
}

// ---------------------------------------------------------------------------
// Scratch tables (static __device__: allocation rules forbid cudaMalloc)
// ---------------------------------------------------------------------------
__device__ float g_wtab [NQ1  * MSZ];   //  2.56 MB : softmax(k . Mk^T)
__device__ float g_fktab[NQ1  * FD ];   //  5.12 MB : bf + Wf_k . k
__device__ float g_etab [NQA1 * VM ];   // 20.5  MB : sigmoid(We . v + be)
__device__ float g_atab [NQA1 * VM ];   // 20.5  MB : tanh(Wa . v + ba)
__device__ float g_WeT  [VD * VM];      // 256 KB : We transposed [j][u]
__device__ float g_WaT  [VD * VM];      // 256 KB : Wa transposed [j][u]

// ---------------------------------------------------------------------------
// Transpose We/Wa (256x256) into [j][u] layout for coalesced build_ea reads.
// grid (8,8,2), block (32,8)
// ---------------------------------------------------------------------------
__global__ void transpose_we_wa(const float* __restrict__ We,
                                const float* __restrict__ Wa)
{
    __shared__ float tile[32][33];
    const float* src = blockIdx.z ? Wa : We;
    float* dst = blockIdx.z ? g_WaT : g_WeT;
    const int bx = blockIdx.x * 32;   // j tile
    const int by = blockIdx.y * 32;   // u tile
    #pragma unroll
    for (int k = 0; k < 4; k++)
        tile[threadIdx.y + k * 8][threadIdx.x] =
            src[(by + threadIdx.y + k * 8) * VD + bx + threadIdx.x];
    __syncthreads();
    #pragma unroll
    for (int k = 0; k < 4; k++)
        dst[(bx + threadIdx.y + k * 8) * VM + by + threadIdx.x] =
            tile[threadIdx.x][threadIdx.y + k * 8];
}

// ---------------------------------------------------------------------------
// Kernel A v2: per-q tables. 32 q-indices per block, block = 256.
// All global loads coalesced; all LDS conflict-free (pad-132 rows).
// smem: k_s[32][128] | Mk_s[64][132] | Wfk_s[128][132] | sc_s[32][64]
// ---------------------------------------------------------------------------
#define WTI 32
#define WFK_SMEM ((WTI*KD + MSZ*132 + FD*132 + WTI*MSZ) * 4)

__global__ void __launch_bounds__(256)
build_wfk_kernel(const float* __restrict__ k_emb, const float* __restrict__ Mk,
                 const float* __restrict__ Wf,    const float* __restrict__ bf)
{
    extern __shared__ float sm[];
    float* k_s   = sm;                              // 4096 floats
    float* Mk_s  = sm + WTI * KD;                   // 8448
    float* Wfk_s = Mk_s + MSZ * 132;                // 16896
    float* sc_s  = Wfk_s + FD * 132;                // 2048

    const int tid  = threadIdx.x;
    const int base = blockIdx.x * WTI;

    for (int idx = tid; idx < WTI * KD; idx += 256) {
        const int i = idx >> 7, j = idx & 127;
        const int gi = min(base + i, NQ1 - 1);
        k_s[i * KD + j] = k_emb[gi * KD + j];
    }
    for (int idx = tid; idx < MSZ * KD; idx += 256) {
        const int m = idx >> 7, j = idx & 127;
        Mk_s[m * 132 + j] = Mk[idx];
    }
    for (int idx = tid; idx < FD * KD; idx += 256) {
        const int ff = idx >> 7, j = idx & 127;
        Wfk_s[ff * 132 + j] = Wf[ff * (KD + VM) + VM + j];
    }
    __syncthreads();

    // ---- scores: thread (m = tid%64, ig = tid/64) handles 8 i's ----------
    {
        const int m = tid & 63, ig = tid >> 6;
        float acc[8];
        #pragma unroll
        for (int ii = 0; ii < 8; ii++) acc[ii] = 0.f;
        #pragma unroll 4
        for (int j4 = 0; j4 < KD / 4; j4++) {
            const float4 mk = *reinterpret_cast<const float4*>(Mk_s + m * 132 + j4 * 4);
            #pragma unroll
            for (int ii = 0; ii < 8; ii++) {
                const float4 kv = *reinterpret_cast<const float4*>(k_s + (ig * 8 + ii) * KD + j4 * 4);
                acc[ii] = fmaf(mk.x, kv.x, fmaf(mk.y, kv.y, fmaf(mk.z, kv.z, fmaf(mk.w, kv.w, acc[ii]))));
            }
        }
        #pragma unroll
        for (int ii = 0; ii < 8; ii++) sc_s[(ig * 8 + ii) * MSZ + m] = acc[ii];
    }
    __syncthreads();

    // ---- softmax: warp w handles i = w, w+8, w+16, w+24 -------------------
    {
        const int lane = tid & 31, w = tid >> 5;
        #pragma unroll
        for (int rep = 0; rep < 4; rep++) {
            const int i = w + rep * 8;
            const float sa = sc_s[i * MSZ + lane];
            const float sb = sc_s[i * MSZ + 32 + lane];
            float mx = fmaxf(sa, sb);
            #pragma unroll
            for (int o = 16; o > 0; o >>= 1) mx = fmaxf(mx, __shfl_xor_sync(0xffffffffu, mx, o));
            const float ea = expf(sa - mx), eb = expf(sb - mx);
            float s = ea + eb;
            #pragma unroll
            for (int o = 16; o > 0; o >>= 1) s += __shfl_xor_sync(0xffffffffu, s, o);
            const float inv = 1.f / s;
            const int gi = base + i;
            if (gi < NQ1) {
                g_wtab[gi * MSZ + lane]      = ea * inv;
                g_wtab[gi * MSZ + 32 + lane] = eb * inv;
            }
        }
    }

    // ---- fk: thread (f = tid%128, h = tid/128) handles 16 i's -------------
    {
        const int ff = tid & 127, h = tid >> 7;
        float fa[16];
        #pragma unroll
        for (int ii = 0; ii < 16; ii++) fa[ii] = 0.f;
        #pragma unroll 2
        for (int j4 = 0; j4 < KD / 4; j4++) {
            const float4 wv = *reinterpret_cast<const float4*>(Wfk_s + ff * 132 + j4 * 4);
            #pragma unroll
            for (int ii = 0; ii < 16; ii++) {
                const float4 kv = *reinterpret_cast<const float4*>(k_s + (h * 16 + ii) * KD + j4 * 4);
                fa[ii] = fmaf(wv.x, kv.x, fmaf(wv.y, kv.y, fmaf(wv.z, kv.z, fmaf(wv.w, kv.w, fa[ii]))));
            }
        }
        const float bff = bf[ff];
        #pragma unroll
        for (int ii = 0; ii < 16; ii++) {
            const int gi = base + h * 16 + ii;
            if (gi < NQ1) g_fktab[gi * FD + ff] = fa[ii] + bff;
        }
    }
}

// ---------------------------------------------------------------------------
// Kernel B v2: per-qa tables from TRANSPOSED weights (coalesced LDG).
// 32 indices per block, block = 256, thread owns output column u.
// ---------------------------------------------------------------------------
#define TI 32
__global__ void __launch_bounds__(256)
build_ea_kernel(const float* __restrict__ v_emb,
                const float* __restrict__ be, const float* __restrict__ ba)
{
    __shared__ float4 v_s[TI * (VD / 4)];   // 32 KB
    const int tid  = threadIdx.x;
    const int base = blockIdx.x * TI;

    for (int idx = tid; idx < TI * (VD / 4); idx += 256) {
        const int i = idx >> 6, j4 = idx & 63;
        const int gi = min(base + i, NQA1 - 1);
        v_s[i * (VD / 4) + j4] = reinterpret_cast<const float4*>(v_emb)[gi * (VD / 4) + j4];
    }
    __syncthreads();

    const int u = tid;
    float acce[TI], acca[TI];
    #pragma unroll
    for (int i = 0; i < TI; i++) { acce[i] = 0.f; acca[i] = 0.f; }

    #pragma unroll 1
    for (int j4 = 0; j4 < VD / 4; j4++) {
        const int j = j4 * 4;
        const float we0 = g_WeT[(j + 0) * VM + u];
        const float we1 = g_WeT[(j + 1) * VM + u];
        const float we2 = g_WeT[(j + 2) * VM + u];
        const float we3 = g_WeT[(j + 3) * VM + u];
        const float wa0 = g_WaT[(j + 0) * VM + u];
        const float wa1 = g_WaT[(j + 1) * VM + u];
        const float wa2 = g_WaT[(j + 2) * VM + u];
        const float wa3 = g_WaT[(j + 3) * VM + u];
        #pragma unroll
        for (int i = 0; i < TI; i++) {
            const float4 v = v_s[i * (VD / 4) + j4];   // warp-broadcast
            acce[i] = fmaf(we0, v.x, fmaf(we1, v.y, fmaf(we2, v.z, fmaf(we3, v.w, acce[i]))));
            acca[i] = fmaf(wa0, v.x, fmaf(wa1, v.y, fmaf(wa2, v.z, fmaf(wa3, v.w, acca[i]))));
        }
    }

    const float bei = be[u], bai = ba[u];
    #pragma unroll
    for (int i = 0; i < TI; i++) {
        const int gi = base + i;
        if (gi < NQA1) {
            g_etab[gi * VM + u] = 1.f / (1.f + expf(-(acce[i] + bei)));
            g_atab[gi * VM + u] = tanhf(acca[i] + bai);
        }
    }
}

// ---------------------------------------------------------------------------
// Output pre-init: out[i] = bp[0] (main kernel atomically accumulates)
// ---------------------------------------------------------------------------
__global__ void init_out_kernel(float* __restrict__ out, const float* __restrict__ bp)
{
    const int i = blockIdx.x * 256 + threadIdx.x;
    if (i < BB * SS) out[i] = bp[0];
}

// ---------------------------------------------------------------------------
// Main sequential kernel: one CTA per batch, 256 threads.
// Thread u owns Mv[:,u] (32 packed f32x2 regs) AND Wf_r[f, h*128:+128]
// (64 packed regs).  3 barriers/step; f32x2 packed FMA throughout.
// ---------------------------------------------------------------------------
__global__ void __launch_bounds__(256, 1)
dkvmn_main_kernel(const int* __restrict__ q,  const int* __restrict__ qa,
                  const float* __restrict__ Wf, const float* __restrict__ Wp,
                  const float* __restrict__ Mv0, float* __restrict__ out)
{
    __shared__ __align__(16) float s_buf[32 * VM];   // 32 KB Wf staging
    __shared__ __align__(16) float s_r[VM];
    __shared__ __align__(16) float s_w[MSZ];
    __shared__ __align__(16) float s_fp[VM];
    __shared__ int s_q[SS], s_qa[SS];

    const int b   = blockIdx.x;
    const int tid = threadIdx.x;
    const int f   = tid & 127;
    const int h   = tid >> 7;

    for (int idx = tid; idx < SS; idx += 256) {
        s_q [idx] = q [b * SS + idx];
        s_qa[idx] = qa[b * SS + idx];
    }

    // ---- Wf_r -> registers via coalesced smem bounce (4 chunks of 32 f) ---
    ull wfr[64];
    #pragma unroll
    for (int c = 0; c < 4; c++) {
        if (c) __syncthreads();
        for (int idx = tid; idx < 32 * VM; idx += 256) {
            const int fr = idx >> 8, u = idx & 255;
            s_buf[fr * VM + u] = Wf[(c * 32 + fr) * (KD + VM) + u];
        }
        __syncthreads();
        if ((f >> 5) == c) {
            const ull* p = reinterpret_cast<const ull*>(s_buf + (f & 31) * VM + h * 128);
            #pragma unroll
            for (int j2 = 0; j2 < 64; j2++) wfr[j2] = p[j2];
        }
    }

    // ---- state: Mv[:,tid] as 32 packed pairs ------------------------------
    ull mv2[32];
    #pragma unroll
    for (int m2 = 0; m2 < 32; m2++)
        mv2[m2] = pk2(Mv0[(2 * m2) * VM + tid], Mv0[(2 * m2 + 1) * VM + tid]);

    const float wp_f = Wp[f];
    __syncthreads();

    // ---- prefetch t = 0 ---------------------------------------------------
    int q0 = s_q[0], qa0 = s_qa[0];
    float e_n  = g_etab [qa0 * VM + tid];
    float a_n  = g_atab [qa0 * VM + tid];
    float fk_n = g_fktab[q0 * FD + f];
    float w_n  = (tid < MSZ) ? g_wtab[q0 * MSZ + tid] : 0.f;

    #pragma unroll 1
    for (int t = 0; t < SS; t++) {
        const float e_c = e_n, a_c = a_n, fk_c = fk_n;
        if (tid < MSZ) s_w[tid] = w_n;
        __syncthreads();                              // (a) s_w ready

        {   // prefetch t+1 (arrives during phases A/B)
            const int tn  = (t + 1 < SS) ? t + 1 : t;
            const int qn  = s_q[tn], qan = s_qa[tn];
            e_n  = g_etab [qan * VM + tid];
            a_n  = g_atab [qan * VM + tid];
            fk_n = g_fktab[qn * FD + f];
            if (tid < MSZ) w_n = g_wtab[qn * MSZ + tid];
        }

        // ---- Phase A: r = w.Mv_old ; Mv += w*(a - e*Mv) (all f32x2) -------
        const ull ne2 = pk2(-e_c, -e_c);
        const ull a2  = pk2(a_c, a_c);
        ull r0 = 0ull, r1 = 0ull, r2 = 0ull, r3 = 0ull;
        const ulonglong2* sw2 = reinterpret_cast<const ulonglong2*>(s_w);
        #pragma unroll
        for (int m4 = 0; m4 < 16; m4++) {
            const ulonglong2 wpair = sw2[m4];         // 2 packed w pairs
            const ull mA = mv2[2 * m4], mB = mv2[2 * m4 + 1];
            const ull tA = fma2(ne2, mA, a2);
            const ull tB = fma2(ne2, mB, a2);
            if (m4 & 1) { r2 = fma2(wpair.x, mA, r2); r3 = fma2(wpair.y, mB, r3); }
            else        { r0 = fma2(wpair.x, mA, r0); r1 = fma2(wpair.y, mB, r1); }
            mv2[2 * m4]     = fma2(wpair.x, tA, mA);
            mv2[2 * m4 + 1] = fma2(wpair.y, tB, mB);
        }
        float x0, x1, x2, x3, x4, x5, x6, x7;
        upk2(r0, x0, x1); upk2(r1, x2, x3); upk2(r2, x4, x5); upk2(r3, x6, x7);
        s_r[tid] = ((x0 + x1) + (x2 + x3)) + ((x4 + x5) + (x6 + x7));
        __syncthreads();                              // (b) s_r ready

        // ---- Phase B: partial f = Wf_r[f, h-half] . r (regs x broadcast) --
        ull acc0 = 0ull, acc1 = 0ull;
        const ulonglong2* sr2 = reinterpret_cast<const ulonglong2*>(s_r + h * 128);
        #pragma unroll
        for (int j4 = 0; j4 < 32; j4++) {
            const ulonglong2 rp = sr2[j4];            // broadcast LDS.128
            acc0 = fma2(wfr[2 * j4],     rp.x, acc0);
            acc1 = fma2(wfr[2 * j4 + 1], rp.y, acc1);
        }
        float y0, y1, y2, y3;
        upk2(acc0, y0, y1); upk2(acc1, y2, y3);
        s_fp[tid] = (y0 + y1) + (y2 + y3);
        __syncthreads();                              // (c) partials ready

        // ---- tanh + Wp + warp-reduce + atomic accumulate ------------------
        if (tid < FD) {
            const float fv = tanhf(s_fp[tid] + s_fp[tid + 128] + fk_c);
            float term = wp_f * fv;
            #pragma unroll
            for (int o = 16; o > 0; o >>= 1) term += __shfl_xor_sync(0xffffffffu, term, o);
            if ((tid & 31) == 0) atomicAdd(out + b * SS + t, term);
        }
    }
}

// ---------------------------------------------------------------------------
// Launch. Inputs: q, qa, k_emb, v_emb, Wf, bf, Wp, bp, We, be, Wa, ba, Mk, Mv0
// ---------------------------------------------------------------------------
extern "C" void kernel_launch(void* const* d_in, const int* in_sizes, int n_in,
                              void* d_out, int out_size)
{
    const int*   q     = (const int*)  d_in[0];
    const int*   qa    = (const int*)  d_in[1];
    const float* k_emb = (const float*)d_in[2];
    const float* v_emb = (const float*)d_in[3];
    const float* Wf    = (const float*)d_in[4];
    const float* bf    = (const float*)d_in[5];
    const float* Wp    = (const float*)d_in[6];
    const float* bp    = (const float*)d_in[7];
    const float* We    = (const float*)d_in[8];
    const float* be    = (const float*)d_in[9];
    const float* Wa    = (const float*)d_in[10];
    const float* ba    = (const float*)d_in[11];
    const float* Mk    = (const float*)d_in[12];
    const float* Mv0   = (const float*)d_in[13];
    float* out = (float*)d_out;

    cudaFuncSetAttribute(build_wfk_kernel,
                         cudaFuncAttributeMaxDynamicSharedMemorySize, WFK_SMEM);

    transpose_we_wa<<<dim3(8, 8, 2), dim3(32, 8)>>>(We, Wa);
    build_wfk_kernel<<<(NQ1 + WTI - 1) / WTI, 256, WFK_SMEM>>>(k_emb, Mk, Wf, bf);
    build_ea_kernel<<<(NQA1 + TI - 1) / TI, 256>>>(v_emb, be, ba);
    init_out_kernel<<<(BB * SS + 255) / 256, 256>>>(out, bp);
    dkvmn_main_kernel<<<BB, 256>>>(q, qa, Wf, Wp, Mv0, out);
}